// round 11
// baseline (speedup 1.0000x reference)
#include <cuda_runtime.h>
#include <cuda_fp16.h>
#include <cstdint>
#include <cstddef>

// Problem constants
#define TT   1024
#define BB   512
#define II   32
#define HH   256
#define OO   32
#define KDIM 288
#define NCHUNK 18        // 288/16 k-chunks

#define NGRP 16          // batch groups (32 rows each; 2 streams of 16)
#define NTHR 256         // 8 warps, warp w owns D rows [16w,16w+16)
#define MROWS 128        // gate rows per CTA, r = 4*j + gate
#define KP   296         // padded halfs per row
#define RB   592         // row bytes (rows mod 128 all distinct -> conflict-free ldsm)

typedef unsigned long long ull;

// Persistent scratch (no allocation allowed)
__device__ __align__(16) __half g_hf16_hi[2][NGRP][2][16][HH]; // [par][grp][stream][bb][j]
__device__ __align__(16) __half g_hf16_lo[2][NGRP][2][16][HH];
__device__ __align__(16) float  g_part[2][NGRP][2][8][16][OO]; // out-proj partials
__device__ unsigned             g_bar[NGRP][2][8];             // per-(group,stream), 32B padded

__global__ void init_kernel() {
    int idx = blockIdx.x * blockDim.x + threadIdx.x;
    if (idx < 131072) {                         // full u32 span of each h array
        ((unsigned*)g_hf16_hi)[idx] = 0u;
        ((unsigned*)g_hf16_lo)[idx] = 0u;
    }
    if (idx < NGRP * 2) g_bar[idx >> 1][idx & 1][0] = 0u;
}

// ---------- helpers ----------
__device__ __forceinline__ void ffma2(ull& acc, ull a, ull b) {
    asm("fma.rn.f32x2 %0, %1, %2, %0;" : "+l"(acc) : "l"(a), "l"(b));
}
__device__ __forceinline__ ull pack2(float a, float b) {
    ull r; asm("mov.b64 %0, {%1, %2};" : "=l"(r) : "f"(a), "f"(b)); return r;
}
__device__ __forceinline__ float2 unpack2(ull v) {
    float2 r; asm("mov.b64 {%0, %1}, %2;" : "=f"(r.x), "=f"(r.y) : "l"(v)); return r;
}
__device__ __forceinline__ unsigned ld_acquire_u32(const unsigned* p) {
    unsigned v;
    asm volatile("ld.acquire.gpu.u32 %0, [%1];" : "=r"(v) : "l"(p));
    return v;
}
__device__ __forceinline__ void red_release_add(unsigned* p, unsigned v) {
    asm volatile("red.release.gpu.global.add.u32 [%0], %1;" :: "l"(p), "r"(v) : "memory");
}
__device__ __forceinline__ float sigf(float x) {
    return __fdividef(1.0f, 1.0f + __expf(-x));
}
__device__ __forceinline__ float tanh_acc(float x) {
    float ax = fabsf(x);
    float e  = __expf(-2.0f * ax);
    float r  = __fdividef(1.0f - e, 1.0f + e);
    return copysignf(r, x);
}
__device__ __forceinline__ uint32_t h2u(__half2 h) { return *reinterpret_cast<uint32_t*>(&h); }

__device__ __forceinline__ void ldsm4(uint32_t* r, uint32_t addr) {
    asm volatile("ldmatrix.sync.aligned.m8n8.x4.shared.b16 {%0,%1,%2,%3}, [%4];"
                 : "=r"(r[0]), "=r"(r[1]), "=r"(r[2]), "=r"(r[3]) : "r"(addr));
}
__device__ __forceinline__ void mma16816(float* d, const uint32_t* a, uint32_t b0, uint32_t b1) {
    asm volatile("mma.sync.aligned.m16n8k16.row.col.f32.f16.f16.f32 "
                 "{%0,%1,%2,%3}, {%4,%5,%6,%7}, {%8,%9}, {%0,%1,%2,%3};"
                 : "+f"(d[0]), "+f"(d[1]), "+f"(d[2]), "+f"(d[3])
                 : "r"(a[0]), "r"(a[1]), "r"(a[2]), "r"(a[3]), "r"(b0), "r"(b1));
}

// smem byte offsets
#define OFF_A_HI   0          // half[128][296] = 75776
#define OFF_A_LO   75776
#define OFF_B0_HI  151552     // half[16][296] = 9472 per tile
#define OFF_B0_LO  161024
#define OFF_B1_HI  170496
#define OFF_B1_LO  179968
#define OFF_GATES  189440     // float[128][20] = 10240
#define OFF_HT     199680     // float[16][36]  = 2304
#define OFF_WOUT2  201984     // ull[32 o][17]  = 4352
#define OFF_BOUT   206336     // float[4]
#define SMEM_BYTES 206400

__global__ void __launch_bounds__(NTHR, 1)
lstm_kernel(const float* __restrict__ x, const float* __restrict__ phys,
            const float* __restrict__ Wih, const float* __restrict__ Whh,
            const float* __restrict__ bih, const float* __restrict__ bhh,
            const float* __restrict__ Wout, const float* __restrict__ bout,
            float* __restrict__ out) {
    extern __shared__ __align__(128) char smem[];
    uint32_t sbase;
    asm("{ .reg .u64 t; cvta.to.shared.u64 t, %1; cvt.u32.u64 %0, t; }" : "=r"(sbase) : "l"(smem));

    float* gates   = (float*)(smem + OFF_GATES);
    float* htile   = (float*)(smem + OFF_HT);
    ull*   wout2_s = (ull*)(smem + OFF_WOUT2);
    float* bout_s  = (float*)(smem + OFF_BOUT);

    const int tid  = threadIdx.x;
    const int cta  = blockIdx.x;
    const int grp  = cta >> 3;
    const int g8   = cta & 7;
    const int b0   = grp * 32;
    const int j0   = g8 * 32;
    const int w    = tid >> 5;
    const int lane = tid & 31;

    // ---- zero all 4 B tiles once (pad cols stay 0 forever) ----
    for (int i = tid; i < (4 * 9472) / 16; i += NTHR)
        ((uint4*)(smem + OFF_B0_HI))[i] = make_uint4(0, 0, 0, 0);

    // ---- A = weights fp16 hi/lo, row r = 4j+gate, 592B stride ----
    for (int i = tid; i < MROWS * KP; i += NTHR) {
        int r = i / KP, k = i - r * KP;
        int j = r >> 2, g = r & 3;
        int grow = g * HH + j0 + j;
        float v = 0.0f;
        if (k < HH)        v = Whh[grow * HH + k];
        else if (k < KDIM) v = Wih[grow * II + (k - HH)];
        __half h = __float2half_rn(v);
        __half l = __float2half_rn(v - __half2float(h));
        *(__half*)(smem + OFF_A_HI + r * RB + k * 2) = h;
        *(__half*)(smem + OFF_A_LO + r * RB + k * 2) = l;
    }
    // Wout pairs over OWN j-slice, all 32 o
    for (int i = tid; i < 32 * 16; i += NTHR) {
        int o = i >> 4, jp = i & 15;
        wout2_s[o * 17 + jp] = pack2(Wout[o * HH + j0 + 2 * jp],
                                     Wout[o * HH + j0 + 2 * jp + 1]);
    }
    if (tid < 4) bout_s[tid] = bout[g8 * 4 + tid];

    // MMA fragment lane mapping (validated R8-R10)
    const int m  = lane >> 3;
    const int r8 = lane & 7;
    const int gq = lane >> 2;
    const int tg = lane & 3;
    const uint32_t aHi = sbase + OFF_A_HI + (16 * w + ((m & 1) << 3) + r8) * RB + ((m >> 1) << 4);
    const uint32_t aLo = aHi + (OFF_A_LO - OFF_A_HI);
    const uint32_t bOff = (((m >> 1) << 3) + r8) * RB + ((m & 1) << 4);
    const uint32_t bHiS[2] = {sbase + OFF_B0_HI + bOff, sbase + OFF_B1_HI + bOff};
    const uint32_t bLoS[2] = {sbase + OFF_B0_LO + bOff, sbase + OFF_B1_LO + bOff};
    const uint32_t bStageS[2] = {sbase + OFF_B0_HI, sbase + OFF_B1_HI};

    // bias folded into D-register init (rows 16w+gq, 16w+gq+8)
    float bias_lo, bias_hi;
    {
        int r1 = 16 * w + gq, r2 = r1 + 8;
        int j1 = r1 >> 2, gg1 = r1 & 3, j2 = r2 >> 2, gg2 = r2 & 3;
        bias_lo = bih[gg1 * HH + j0 + j1] + bhh[gg1 * HH + j0 + j1];
        bias_hi = bih[gg2 * HH + j0 + j2] + bhh[gg2 * HH + j0 + j2];
    }

    float c[2][2] = {{0.f, 0.f}, {0.f, 0.f}};   // cell state per stream: (j=tid>>3, bb=2q,2q+1)
    __syncthreads();

    // staging / writeback thread maps
    const int bb16 = tid >> 4;       // 0..15
    const int k16  = tid & 15;       // 0..15

    for (int t = 0; t <= TT; ++t) {
#pragma unroll
        for (int st = 0; st < 2; ++st) {
            // ---- peer-independent prefetches BEFORE the spin ----
            uint32_t xhu = 0, xlu = 0;
            if (t < TT) {
                float2 xv = *(const float2*)(x + ((size_t)t * BB + b0 + 16 * st + bb16) * II + 2 * k16);
                __half2 xh = __floats2half2_rn(xv.x, xv.y);
                float2 xf = __half22float2(xh);
                __half2 xl = __floats2half2_rn(xv.x - xf.x, xv.y - xf.y);
                xhu = h2u(xh); xlu = h2u(xl);
            }
            float phv = 0.0f;
            if (t > 0 && tid < 64)
                phv = phys[((size_t)(t - 1) * BB + b0 + 16 * st + (tid >> 2)) * OO + g8 * 4 + (tid & 3)];

            // ---- stream barrier: per-warp acquire spin (64 arrivals/step) ----
            if (t > 0) {
                if (lane == 0) {
                    unsigned target = 64u * (unsigned)t;
                    while (ld_acquire_u32(&g_bar[grp][st][0]) < target) { }
                }
                __syncwarp();
            }

            if (t < TT) {
                // ---- stage h(t): pure fp16 copy ----
                const uint4* hi4 = (const uint4*)&g_hf16_hi[t & 1][grp][st][bb16][k16 * 16];
                const uint4* lo4 = (const uint4*)&g_hf16_lo[t & 1][grp][st][bb16][k16 * 16];
                char* dhi = (char*)smem + (bStageS[st] - sbase) + bb16 * RB + k16 * 32;
                char* dlo = dhi + 9472;
                *(uint4*)(dhi)      = hi4[0];
                *(uint4*)(dhi + 16) = hi4[1];
                *(uint4*)(dlo)      = lo4[0];
                *(uint4*)(dlo + 16) = lo4[1];
                // stage x(t) (pre-converted) into B cols 256..287
                *(uint32_t*)(dhi - k16 * 32 + 512 + k16 * 4) = xhu;
                *(uint32_t*)(dlo - k16 * 32 + 512 + k16 * 4) = xlu;
            }

            if (t == TT) {
                // final output for step TT-1 of this stream
                if (tid < 64) {
                    int bq = tid >> 2, o = tid & 3, oc = g8 * 4 + o;
                    float rnn = bout_s[o];
                    const float* pp = &g_part[t & 1][grp][st][0][bq][oc];
#pragma unroll
                    for (int p = 0; p < 8; ++p) rnn += pp[(size_t)p * 16 * OO];
                    size_t oi = ((size_t)(b0 + 16 * st + bq) * TT + (t - 1)) * OO + oc;
                    out[oi] = phv + rnn;
                    out[(size_t)BB * TT * OO + oi] = rnn;
                }
                continue;
            }
            __syncthreads();

            // ---- gate GEMM: 3-pass fp16-split, N=16 ----
            float d[2][4];
            d[0][0] = bias_lo; d[0][1] = bias_lo; d[0][2] = bias_hi; d[0][3] = bias_hi;
            d[1][0] = bias_lo; d[1][1] = bias_lo; d[1][2] = bias_hi; d[1][3] = bias_hi;
            const uint32_t bH = bHiS[st], bL = bLoS[st];
#pragma unroll 3
            for (int kc = 0; kc < NCHUNK; ++kc) {
                uint32_t a[4], a2[4], qh[4], ql[4];
                ldsm4(a,  aHi + kc * 32);
                ldsm4(qh, bH  + kc * 32);
                ldsm4(ql, bL  + kc * 32);
                ldsm4(a2, aLo + kc * 32);
                mma16816(d[0], a,  qh[0], qh[1]);
                mma16816(d[1], a,  qh[2], qh[3]);
                mma16816(d[0], a,  ql[0], ql[1]);
                mma16816(d[1], a,  ql[2], ql[3]);
                mma16816(d[0], a2, qh[0], qh[1]);
                mma16816(d[1], a2, qh[2], qh[3]);
            }
            // D -> gates[row][bb] (stride 20)
            {
                float* glo = gates + (16 * w + gq) * 20 + 2 * tg;
                float* ghi = glo + 8 * 20;
#pragma unroll
                for (int nt = 0; nt < 2; ++nt) {
                    glo[8 * nt] = d[nt][0]; glo[8 * nt + 1] = d[nt][1];
                    ghi[8 * nt] = d[nt][2]; ghi[8 * nt + 1] = d[nt][3];
                }
            }

            // ---- output for step t-1 of this stream (overlaps gates sync) ----
            if (t > 0 && tid < 64) {
                int bq = tid >> 2, o = tid & 3, oc = g8 * 4 + o;
                float rnn = bout_s[o];
                const float* pp = &g_part[t & 1][grp][st][0][bq][oc];
#pragma unroll
                for (int p = 0; p < 8; ++p) rnn += pp[(size_t)p * 16 * OO];
                size_t oi = ((size_t)(b0 + 16 * st + bq) * TT + (t - 1)) * OO + oc;
                out[oi] = phv + rnn;
                out[(size_t)BB * TT * OO + oi] = rnn;
            }
            __syncthreads();

            // ---- LSTM epilogue: thread = (j = tid>>3, bb = 2q, 2q+1) ----
            {
                int j = tid >> 3, q = tid & 7;
                const float* gr = gates + (4 * j) * 20 + 2 * q;
                float2 vi = *(const float2*)(gr);
                float2 vf = *(const float2*)(gr + 20);
                float2 vg = *(const float2*)(gr + 40);
                float2 vo = *(const float2*)(gr + 60);
                float gi_[2] = {vi.x, vi.y}, gf_[2] = {vf.x, vf.y};
                float gg_[2] = {vg.x, vg.y}, go_[2] = {vo.x, vo.y};
#pragma unroll
                for (int i = 0; i < 2; ++i) {
                    float ig = sigf(gi_[i]), fg = sigf(gf_[i]);
                    float gt = tanh_acc(gg_[i]), og = sigf(go_[i]);
                    float cn = fg * c[st][i] + ig * gt;
                    c[st][i] = cn;
                    htile[(2 * q + i) * 36 + j] = og * tanh_acc(cn);
                }
            }
            __syncthreads();

            // ---- writeback h fp16 hi/lo + out-proj partial ----
            {
                int jq = k16 * 2;
                float2 hv = *(const float2*)(htile + bb16 * 36 + jq);
                __half2 hh = __floats2half2_rn(hv.x, hv.y);
                float2 qf = __half22float2(hh);
                __half2 hl = __floats2half2_rn(hv.x - qf.x, hv.y - qf.y);
                *(uint32_t*)(&g_hf16_hi[(t + 1) & 1][grp][st][bb16][j0 + jq]) = h2u(hh);
                *(uint32_t*)(&g_hf16_lo[(t + 1) & 1][grp][st][bb16][j0 + jq]) = h2u(hl);
            }
            {
                int o2 = k16 * 2;
                const ull* hrow2 = (const ull*)(htile + bb16 * 36);
                ull pa0 = 0ull, pa1 = 0ull;
#pragma unroll
                for (int jp = 0; jp < 16; ++jp) {
                    ull h2 = hrow2[jp];
                    ffma2(pa0, h2, wout2_s[(o2 + 0) * 17 + jp]);
                    ffma2(pa1, h2, wout2_s[(o2 + 1) * 17 + jp]);
                }
                float2 q0 = unpack2(pa0), q1 = unpack2(pa1);
                *(float2*)(&g_part[(t + 1) & 1][grp][st][g8][bb16][o2]) =
                    make_float2(q0.x + q0.y, q1.x + q1.y);
            }
            __syncwarp();
            if (lane == 0) red_release_add(&g_bar[grp][st][0], 1u);
        }
        if (t == TT) break;
    }
}

extern "C" void kernel_launch(void* const* d_in, const int* in_sizes, int n_in,
                              void* d_out, int out_size) {
    const float* x    = (const float*)d_in[0];
    const float* phys = (const float*)d_in[1];
    const float* Wih  = (const float*)d_in[2];
    const float* Whh  = (const float*)d_in[3];
    const float* bih  = (const float*)d_in[4];
    const float* bhh  = (const float*)d_in[5];
    const float* Wout = (const float*)d_in[6];
    const float* bout = (const float*)d_in[7];
    float* out = (float*)d_out;

    cudaFuncSetAttribute(lstm_kernel,
                         cudaFuncAttributeMaxDynamicSharedMemorySize,
                         SMEM_BYTES);

    init_kernel<<<(131072 + 255) / 256, 256>>>();
    lstm_kernel<<<NGRP * 8, NTHR, SMEM_BYTES>>>(x, phys, Wih, Whh, bih, bhh,
                                                Wout, bout, out);
}

// round 12
// speedup vs baseline: 1.0183x; 1.0183x over previous
#include <cuda_runtime.h>
#include <cuda_fp16.h>
#include <cstdint>
#include <cstddef>

// Problem constants
#define TT   1024
#define BB   512
#define II   32
#define HH   256
#define OO   32
#define KDIM 288
#define NCHUNK 18        // 288/16 k-chunks

#define NGRP 16          // batch groups (32 rows each)
#define GCTA 16          // CTAs per group, each owns 16 j
#define NTHR 256         // 8 warps
#define MROWS 64         // gate rows per CTA, r = 4*jj + gate
#define KP   296         // padded halfs per row
#define RB   592         // row bytes (rows mod 128 all distinct -> conflict-free ldsm)

typedef unsigned long long ull;

// Persistent scratch (no allocation allowed)
__device__ __align__(16) __half g_hf16[2][NGRP][32][HH];        // h fp16 [par][grp][b][j]
__device__ __align__(16) float  g_part[2][NGRP][GCTA][32][OO];  // out-proj partials
__device__ unsigned             g_bar[NGRP];

__global__ void init_kernel() {
    int idx = blockIdx.x * blockDim.x + threadIdx.x;
    if (idx < 131072) ((unsigned*)g_hf16)[idx] = 0u;   // zero both parities
    if (idx < NGRP) g_bar[idx] = 0u;
}

// ---------- helpers ----------
__device__ __forceinline__ void ffma2(ull& acc, ull a, ull b) {
    asm("fma.rn.f32x2 %0, %1, %2, %0;" : "+l"(acc) : "l"(a), "l"(b));
}
__device__ __forceinline__ ull pack2(float a, float b) {
    ull r; asm("mov.b64 %0, {%1, %2};" : "=l"(r) : "f"(a), "f"(b)); return r;
}
__device__ __forceinline__ float2 unpack2(ull v) {
    float2 r; asm("mov.b64 {%0, %1}, %2;" : "=f"(r.x), "=f"(r.y) : "l"(v)); return r;
}
__device__ __forceinline__ unsigned ld_acquire_u32(const unsigned* p) {
    unsigned v;
    asm volatile("ld.acquire.gpu.u32 %0, [%1];" : "=r"(v) : "l"(p));
    return v;
}
__device__ __forceinline__ void red_release_add(unsigned* p, unsigned v) {
    asm volatile("red.release.gpu.global.add.u32 [%0], %1;" :: "l"(p), "r"(v) : "memory");
}
__device__ __forceinline__ float sigf(float x) {
    return __fdividef(1.0f, 1.0f + __expf(-x));
}
__device__ __forceinline__ float tanh_acc(float x) {
    float ax = fabsf(x);
    float e  = __expf(-2.0f * ax);
    float r  = __fdividef(1.0f - e, 1.0f + e);
    return copysignf(r, x);
}
__device__ __forceinline__ uint32_t h2u(__half2 h) { return *reinterpret_cast<uint32_t*>(&h); }

__device__ __forceinline__ void ldsm4(uint32_t* r, uint32_t addr) {
    asm volatile("ldmatrix.sync.aligned.m8n8.x4.shared.b16 {%0,%1,%2,%3}, [%4];"
                 : "=r"(r[0]), "=r"(r[1]), "=r"(r[2]), "=r"(r[3]) : "r"(addr));
}
__device__ __forceinline__ void mma16816(float* d, const uint32_t* a, uint32_t b0, uint32_t b1) {
    asm volatile("mma.sync.aligned.m16n8k16.row.col.f32.f16.f16.f32 "
                 "{%0,%1,%2,%3}, {%4,%5,%6,%7}, {%8,%9}, {%0,%1,%2,%3};"
                 : "+f"(d[0]), "+f"(d[1]), "+f"(d[2]), "+f"(d[3])
                 : "r"(a[0]), "r"(a[1]), "r"(a[2]), "r"(a[3]), "r"(b0), "r"(b1));
}

// smem byte offsets
#define OFF_A_HI   0          // half[64][296] = 37888
#define OFF_A_LO   37888      // -> 75776
#define OFF_B_HI   75776      // half[32][296] = 18944 -> 94720
#define OFF_GATES  94720      // float[64][36] = 9216 -> 103936
#define OFF_HT     103936     // float[32][18] = 2304 -> 106240
#define OFF_WOUT2  106240     // ull[32 o][9]  = 2304 -> 108544
#define OFF_BOUT   108544     // float[32]     = 128
#define SMEM_BYTES 108672

__global__ void __launch_bounds__(NTHR, 2)
lstm_kernel(const float* __restrict__ x, const float* __restrict__ phys,
            const float* __restrict__ Wih, const float* __restrict__ Whh,
            const float* __restrict__ bih, const float* __restrict__ bhh,
            const float* __restrict__ Wout, const float* __restrict__ bout,
            float* __restrict__ out) {
    extern __shared__ __align__(128) char smem[];
    uint32_t sbase;
    asm("{ .reg .u64 t; cvta.to.shared.u64 t, %1; cvt.u32.u64 %0, t; }" : "=r"(sbase) : "l"(smem));

    float* gates   = (float*)(smem + OFF_GATES);
    float* htile   = (float*)(smem + OFF_HT);
    ull*   wout2_s = (ull*)(smem + OFF_WOUT2);
    float* bout_s  = (float*)(smem + OFF_BOUT);

    const int tid  = threadIdx.x;
    const int cta  = blockIdx.x;
    const int grp  = cta >> 4;        // batch group 0..15
    const int g16  = cta & 15;        // j-slice 0..15
    const int b0   = grp * 32;
    const int j0   = g16 * 16;
    const int w    = tid >> 5;
    const int lane = tid & 31;
    const int b    = tid >> 3;        // batch row 0..31 (staging/writeback map)
    const int s    = tid & 7;         // slice 0..7

    // ---- zero B tile once (pad cols 288..295 stay 0 forever) ----
    for (int i = tid; i < 18944 / 16; i += NTHR)
        ((uint4*)(smem + OFF_B_HI))[i] = make_uint4(0, 0, 0, 0);

    // ---- A = weights fp16 hi/lo, row r = 4jj+gate, 592B stride ----
    for (int i = tid; i < MROWS * KP; i += NTHR) {
        int r = i / KP, k = i - r * KP;
        int jj = r >> 2, g = r & 3;
        int grow = g * HH + j0 + jj;
        float v = 0.0f;
        if (k < HH)        v = Whh[grow * HH + k];
        else if (k < KDIM) v = Wih[grow * II + (k - HH)];
        __half h = __float2half_rn(v);
        __half l = __float2half_rn(v - __half2float(h));
        *(__half*)(smem + OFF_A_HI + r * RB + k * 2) = h;
        *(__half*)(smem + OFF_A_LO + r * RB + k * 2) = l;
    }
    // Wout pairs over OWN 16 j, all 32 o
    for (int i = tid; i < 32 * 8; i += NTHR) {
        int o = i >> 3, jp = i & 7;
        wout2_s[o * 9 + jp] = pack2(Wout[o * HH + j0 + 2 * jp],
                                    Wout[o * HH + j0 + 2 * jp + 1]);
    }
    if (tid < 32) bout_s[tid] = bout[tid];

    // MMA fragment lane mapping; warp: wm = M-quarter, wn = N-half
    const int m  = lane >> 3;
    const int r8 = lane & 7;
    const int gq = lane >> 2;
    const int tg = lane & 3;
    const int wm = w & 3;
    const int wn = w >> 2;
    const uint32_t aHi = sbase + OFF_A_HI + (16 * wm + ((m & 1) << 3) + r8) * RB + ((m >> 1) << 4);
    const uint32_t aLo = aHi + (OFF_A_LO - OFF_A_HI);
    const uint32_t bAd = sbase + OFF_B_HI + (16 * wn + ((m >> 1) << 3) + r8) * RB + ((m & 1) << 4);

    // bias folded into D-register init (rows 16wm+gq, 16wm+gq+8)
    float bias_lo, bias_hi;
    {
        int r1 = 16 * wm + gq, r2 = r1 + 8;
        int j1 = r1 >> 2, gg1 = r1 & 3, j2 = r2 >> 2, gg2 = r2 & 3;
        bias_lo = bih[gg1 * HH + j0 + j1] + bhh[gg1 * HH + j0 + j1];
        bias_hi = bih[gg2 * HH + j0 + j2] + bhh[gg2 * HH + j0 + j2];
    }

    float c[2] = {0.f, 0.f};          // cell state: (jj = tid>>4, batches 2q, 2q+1)
    __syncthreads();

    for (int t = 0; t <= TT; ++t) {
        // ---- peer-independent prefetch + convert BEFORE the spin ----
        uint32_t xu0 = 0, xu1 = 0;
        if (t < TT) {
            float4 xv = *(const float4*)(x + ((size_t)t * BB + b0 + b) * II + 4 * s);
            xu0 = h2u(__floats2half2_rn(xv.x, xv.y));
            xu1 = h2u(__floats2half2_rn(xv.z, xv.w));
        }
        float phv = 0.0f;
        if (t > 0 && tid < 64)
            phv = phys[((size_t)(t - 1) * BB + b0 + (tid >> 1)) * OO + 2 * g16 + (tid & 1)];

        // ---- group barrier: per-warp acquire spin (128 arrivals/step) ----
        if (t > 0) {
            if (lane == 0) {
                unsigned target = 128u * (unsigned)t;
                while (ld_acquire_u32(&g_bar[grp]) < target) { }
            }
            __syncwarp();
        }

        if (t < TT) {
            // ---- stage h(t): pure fp16 copy ----
            const uint4* hi4 = (const uint4*)&g_hf16[t & 1][grp][b][s * 32];
            char* dhi = smem + OFF_B_HI + b * RB + s * 64;
            *(uint4*)(dhi)      = hi4[0];
            *(uint4*)(dhi + 16) = hi4[1];
            *(uint4*)(dhi + 32) = hi4[2];
            *(uint4*)(dhi + 48) = hi4[3];
            // stage x(t) (pre-converted) into B cols 256..287
            *(uint2*)(smem + OFF_B_HI + b * RB + 512 + s * 8) = make_uint2(xu0, xu1);
        }

        if (t == TT) {
            if (tid < 64) {          // final output for step TT-1
                int bq = tid >> 1, oc = 2 * g16 + (tid & 1);
                float rnn = bout_s[oc];
                const float* pp = &g_part[t & 1][grp][0][bq][oc];
#pragma unroll
                for (int p = 0; p < GCTA; ++p) rnn += pp[(size_t)p * 32 * OO];
                size_t oi = ((size_t)(b0 + bq) * TT + (t - 1)) * OO + oc;
                out[oi] = phv + rnn;
                out[(size_t)BB * TT * OO + oi] = rnn;
            }
            break;
        }
        __syncthreads();

        // ---- gate GEMM: 2-pass (Whi + Wlo) x h_fp16 ----
        float d[2][4];
        d[0][0] = bias_lo; d[0][1] = bias_lo; d[0][2] = bias_hi; d[0][3] = bias_hi;
        d[1][0] = bias_lo; d[1][1] = bias_lo; d[1][2] = bias_hi; d[1][3] = bias_hi;
#pragma unroll 6
        for (int kc = 0; kc < NCHUNK; ++kc) {
            uint32_t a[4], a2[4], q[4];
            ldsm4(a,  aHi + kc * 32);
            ldsm4(q,  bAd + kc * 32);
            ldsm4(a2, aLo + kc * 32);
            mma16816(d[0], a,  q[0], q[1]);
            mma16816(d[1], a,  q[2], q[3]);
            mma16816(d[0], a2, q[0], q[1]);
            mma16816(d[1], a2, q[2], q[3]);
        }
        // D -> gates[row][batch] (stride 36); warp covers batches 16wn..16wn+16
        {
            float* glo = gates + (16 * wm + gq) * 36 + 16 * wn + 2 * tg;
            float* ghi = glo + 8 * 36;
#pragma unroll
            for (int nt = 0; nt < 2; ++nt) {
                glo[8 * nt] = d[nt][0]; glo[8 * nt + 1] = d[nt][1];
                ghi[8 * nt] = d[nt][2]; ghi[8 * nt + 1] = d[nt][3];
            }
        }

        // ---- output for step t-1 (overlaps gates sync) ----
        if (t > 0 && tid < 64) {
            int bq = tid >> 1, oc = 2 * g16 + (tid & 1);
            float rnn = bout_s[oc];
            const float* pp = &g_part[t & 1][grp][0][bq][oc];
#pragma unroll
            for (int p = 0; p < GCTA; ++p) rnn += pp[(size_t)p * 32 * OO];
            size_t oi = ((size_t)(b0 + bq) * TT + (t - 1)) * OO + oc;
            out[oi] = phv + rnn;
            out[(size_t)BB * TT * OO + oi] = rnn;
        }
        __syncthreads();

        // ---- LSTM epilogue: thread = (jj = tid>>4, batches 2q, 2q+1) ----
        {
            int jj = tid >> 4, q = tid & 15;
            const float* gr = gates + (4 * jj) * 36 + 2 * q;
            float2 vi = *(const float2*)(gr);
            float2 vf = *(const float2*)(gr + 36);
            float2 vg = *(const float2*)(gr + 72);
            float2 vo = *(const float2*)(gr + 108);
            float gi_[2] = {vi.x, vi.y}, gf_[2] = {vf.x, vf.y};
            float gg_[2] = {vg.x, vg.y}, go_[2] = {vo.x, vo.y};
#pragma unroll
            for (int i = 0; i < 2; ++i) {
                float ig = sigf(gi_[i]), fg = sigf(gf_[i]);
                float gt = tanh_acc(gg_[i]), og = sigf(go_[i]);
                float cn = fg * c[i] + ig * gt;
                c[i] = cn;
                htile[(2 * q + i) * 18 + jj] = og * tanh_acc(cn);
            }
        }
        __syncthreads();

        // ---- writeback h fp16 (2 j per thread) + out-proj partial (4 o) ----
        {
            float2 hv = *(const float2*)(htile + b * 18 + 2 * s);
            *(uint32_t*)(&g_hf16[(t + 1) & 1][grp][b][j0 + 2 * s]) =
                h2u(__floats2half2_rn(hv.x, hv.y));
        }
        {
            int o4 = 4 * s;
            const ull* hrow2 = (const ull*)(htile + b * 18);
            ull pa0 = 0ull, pa1 = 0ull, pa2 = 0ull, pa3 = 0ull;
#pragma unroll
            for (int jp = 0; jp < 8; ++jp) {
                ull h2 = hrow2[jp];
                ffma2(pa0, h2, wout2_s[(o4 + 0) * 9 + jp]);
                ffma2(pa1, h2, wout2_s[(o4 + 1) * 9 + jp]);
                ffma2(pa2, h2, wout2_s[(o4 + 2) * 9 + jp]);
                ffma2(pa3, h2, wout2_s[(o4 + 3) * 9 + jp]);
            }
            float2 q0 = unpack2(pa0), q1 = unpack2(pa1);
            float2 q2 = unpack2(pa2), q3 = unpack2(pa3);
            *(float4*)(&g_part[(t + 1) & 1][grp][g16][b][o4]) =
                make_float4(q0.x + q0.y, q1.x + q1.y, q2.x + q2.y, q3.x + q3.y);
        }
        __syncwarp();
        if (lane == 0) red_release_add(&g_bar[grp], 1u);
    }
}

extern "C" void kernel_launch(void* const* d_in, const int* in_sizes, int n_in,
                              void* d_out, int out_size) {
    const float* x    = (const float*)d_in[0];
    const float* phys = (const float*)d_in[1];
    const float* Wih  = (const float*)d_in[2];
    const float* Whh  = (const float*)d_in[3];
    const float* bih  = (const float*)d_in[4];
    const float* bhh  = (const float*)d_in[5];
    const float* Wout = (const float*)d_in[6];
    const float* bout = (const float*)d_in[7];
    float* out = (float*)d_out;

    cudaFuncSetAttribute(lstm_kernel,
                         cudaFuncAttributeMaxDynamicSharedMemorySize,
                         SMEM_BYTES);

    init_kernel<<<(131072 + 255) / 256, 256>>>();
    lstm_kernel<<<NGRP * GCTA, NTHR, SMEM_BYTES>>>(x, phys, Wih, Whh, bih, bhh,
                                                   Wout, bout, out);
}